// round 11
// baseline (speedup 1.0000x reference)
#include <cuda_runtime.h>
#include <cuda_fp16.h>
#include <cstdint>

#define H 64
#define NN 100000
#define NE 1600000

// device-global scratch (no allocation allowed)
__device__ float g_mi[(size_t)NN * H];
__device__ half  g_p[(size_t)NN * 128];   // [P1 | P2] per node (edge MLP layer-1)
__device__ float g_q[(size_t)NN * 64];    // h@Wn1_bot + bn1 (node MLP layer-1 part)

__device__ __forceinline__ float fast_sigmoid(float z) {
    return 1.0f / (1.0f + __expf(-z));
}
__device__ __forceinline__ void mma_f16(float c[4], const unsigned a[4], const unsigned b[2]) {
    asm volatile("mma.sync.aligned.m16n8k16.row.col.f32.f16.f16.f32 "
        "{%0,%1,%2,%3}, {%4,%5,%6,%7}, {%8,%9}, {%0,%1,%2,%3};"
        : "+f"(c[0]), "+f"(c[1]), "+f"(c[2]), "+f"(c[3])
        : "r"(a[0]), "r"(a[1]), "r"(a[2]), "r"(a[3]), "r"(b[0]), "r"(b[1]));
}
__device__ __forceinline__ void ldmx4(unsigned a[4], unsigned saddr) {
    asm volatile("ldmatrix.sync.aligned.m8n8.x4.shared.b16 {%0,%1,%2,%3}, [%4];"
        : "=r"(a[0]), "=r"(a[1]), "=r"(a[2]), "=r"(a[3]) : "r"(saddr));
}
__device__ __forceinline__ unsigned h2u(half2 v) { return *reinterpret_cast<unsigned*>(&v); }
__device__ __forceinline__ void cpasync16(unsigned dst, const void* src) {
    asm volatile("cp.async.cg.shared.global [%0], [%1], 16;" :: "r"(dst), "l"(src));
}
__device__ __forceinline__ unsigned hadd2u(unsigned a, unsigned b) {
    unsigned r; asm("add.f16x2 %0, %1, %2;" : "=r"(r) : "r"(a), "r"(b)); return r;
}
__device__ __forceinline__ unsigned hrelu2u(unsigned a) {
    unsigned r; asm("max.f16x2 %0, %1, %2;" : "=r"(r) : "r"(a), "r"(0u)); return r;
}

// ---------------------------------------------------------------------------
// Precompute per node (64 nodes/block):
//   g_p[n][0:64]   = h[n] @ We1_top      (fp16)
//   g_p[n][64:128] = h[n] @ We1_bot      (fp16)
//   g_q[n][0:64]   = h[n] @ Wn1_bot + bn1 (fp32)
// ---------------------------------------------------------------------------
__global__ void __launch_bounds__(256) precompute_kernel(
    const float* __restrict__ h, const float* __restrict__ We1,
    const float* __restrict__ Wn1, const float* __restrict__ bn1)
{
    __shared__ half sAh[64 * 72];
    const int tid = threadIdx.x;
    const int warp = tid >> 5, lane = tid & 31;
    const int lane4 = lane & 3, laned4 = lane >> 2;
    const int wm = warp & 1, wn = warp >> 1;   // 32 rows x 48 out-cols per warp

    unsigned wb[4][6][2];
#pragma unroll
    for (int kt = 0; kt < 4; kt++)
#pragma unroll
        for (int nt = 0; nt < 6; nt++) {
            int j = wn * 48 + nt * 8 + laned4;      // 0..191 output col
            int k = kt * 16 + 2 * lane4;
            float w00, w01, w10, w11;
            if (j < 128) {
                int kr = k + ((j >= 64) ? 64 : 0);
                int jc = j & 63;
                w00 = We1[kr * 64 + jc];       w01 = We1[(kr + 1) * 64 + jc];
                w10 = We1[(kr + 8) * 64 + jc]; w11 = We1[(kr + 9) * 64 + jc];
            } else {
                int jc = j - 128;
                w00 = Wn1[(k + 64) * 64 + jc];     w01 = Wn1[(k + 65) * 64 + jc];
                w10 = Wn1[(k + 72) * 64 + jc];     w11 = Wn1[(k + 73) * 64 + jc];
            }
            wb[kt][nt][0] = h2u(__floats2half2_rn(w00, w01));
            wb[kt][nt][1] = h2u(__floats2half2_rn(w10, w11));
        }

    const int node0 = blockIdx.x * 64;
    {
        int nd = tid >> 2, q = tid & 3;
        if (node0 + nd < NN) {
            const float* src = h + (size_t)(node0 + nd) * H + q * 16;
            half* dst = sAh + nd * 72 + q * 16;
#pragma unroll
            for (int j = 0; j < 4; j++) {
                float4 v = *reinterpret_cast<const float4*>(src + j * 4);
                *reinterpret_cast<half2*>(dst + j * 4)     = __floats2half2_rn(v.x, v.y);
                *reinterpret_cast<half2*>(dst + j * 4 + 2) = __floats2half2_rn(v.z, v.w);
            }
        }
    }
    __syncthreads();

    const int al = lane & 15, ah = lane >> 4;
    unsigned abase = (unsigned)__cvta_generic_to_shared(sAh) + ((wm * 32 + al) * 72 + ah * 8) * 2;
    float acc[2][6][4] = {};
#pragma unroll
    for (int kt = 0; kt < 4; kt++)
#pragma unroll
        for (int mt = 0; mt < 2; mt++) {
            unsigned a[4];
            ldmx4(a, abase + (mt * 16 * 72 + kt * 16) * 2);
#pragma unroll
            for (int nt = 0; nt < 6; nt++)
                mma_f16(acc[mt][nt], a, wb[kt][nt]);
        }
#pragma unroll
    for (int mt = 0; mt < 2; mt++)
#pragma unroll
        for (int nt = 0; nt < 6; nt++) {
            int r = wm * 32 + mt * 16 + laned4;
            int c = wn * 48 + nt * 8 + 2 * lane4;
            if (c < 128) {
                if (node0 + r < NN)
                    *reinterpret_cast<half2*>(g_p + (size_t)(node0 + r) * 128 + c) =
                        __floats2half2_rn(acc[mt][nt][0], acc[mt][nt][1]);
                if (node0 + r + 8 < NN)
                    *reinterpret_cast<half2*>(g_p + (size_t)(node0 + r + 8) * 128 + c) =
                        __floats2half2_rn(acc[mt][nt][2], acc[mt][nt][3]);
            } else {
                int cq = c - 128;
                float b0 = bn1[cq], b1 = bn1[cq + 1];
                if (node0 + r < NN)
                    *reinterpret_cast<float2*>(g_q + (size_t)(node0 + r) * 64 + cq) =
                        make_float2(acc[mt][nt][0] + b0, acc[mt][nt][1] + b1);
                if (node0 + r + 8 < NN)
                    *reinterpret_cast<float2*>(g_q + (size_t)(node0 + r + 8) * 64 + cq) =
                        make_float2(acc[mt][nt][2] + b0, acc[mt][nt][3] + b1);
            }
        }
}

// ---------------------------------------------------------------------------
// Edge kernel: gather P1[dst],P2[src]; fused relu(P1+P2+b) -> GEMM2; v4 scatter
// ---------------------------------------------------------------------------
#define TILE_E 128        // 2 subtiles of 64
#define PAD_P 136         // halves/row (272B): conflict-free ldmatrix
#define SP_BYTES (64 * PAD_P * 2)
#define EK_SMEM_BYTES (4*SP_BYTES + 2*128*4*3)

__global__ void __launch_bounds__(256, 2) edge_mma_kernel(
    const float* __restrict__ x,
    const int* __restrict__ edge_index,
    const float* __restrict__ be1,
    const float* __restrict__ We2, const float* __restrict__ be2,
    const float* __restrict__ Winf, const float* __restrict__ binf)
{
    extern __shared__ char smraw[];
    half*  sP   = (half*)smraw;                      // [4][64][136]  (buf*2+sub)
    float* sDis = (float*)(sP + 4 * 64 * PAD_P);     // [2][128]
    float* sE   = sDis + 256;                        // [2][128]
    int*   sDst = (int*)(sE + 256);                  // [2][128]

    const int tid  = threadIdx.x;
    const int warp = tid >> 5, lane = tid & 31;
    const int lane4 = lane & 3, laned4 = lane >> 2;
    const int wm = warp & 1;       // rows 32*wm .. +32 (within subtile)
    const int wn = warp >> 1;      // cols 16*wn .. +16

    unsigned wb2[4][2][2];
#pragma unroll
    for (int kt = 0; kt < 4; kt++)
#pragma unroll
        for (int nt = 0; nt < 2; nt++) {
            int n = wn * 16 + nt * 8 + laned4;
            int k = kt * 16 + 2 * lane4;
            wb2[kt][nt][0] = h2u(__floats2half2_rn(We2[k * 64 + n], We2[(k + 1) * 64 + n]));
            wb2[kt][nt][1] = h2u(__floats2half2_rn(We2[(k + 8) * 64 + n], We2[(k + 9) * 64 + n]));
        }
    unsigned bias1u[4][2];
#pragma unroll
    for (int kt = 0; kt < 4; kt++) {
        int k = kt * 16 + 2 * lane4;
        bias1u[kt][0] = h2u(__floats2half2_rn(be1[k], be1[k + 1]));
        bias1u[kt][1] = h2u(__floats2half2_rn(be1[k + 8], be1[k + 9]));
    }
    float bias2[2][2], wf[2][2];
#pragma unroll
    for (int nt = 0; nt < 2; nt++) {
        int c = wn * 16 + nt * 8 + 2 * lane4;
        bias2[nt][0] = be2[c]; bias2[nt][1] = be2[c + 1];
        wf[nt][0]    = Winf[c]; wf[nt][1]   = Winf[c + 1];
    }
    const float binf0 = binf[0];

    unsigned sP_s = (unsigned)__cvta_generic_to_shared(sP);
    const int al = lane & 15, ah = lane >> 4;
    const unsigned poff_l = (unsigned)(((wm * 32 + al) * PAD_P + ah * 8) * 2);

    const int se = tid >> 2;
    const int sp = tid & 3;

    auto prefetch = [&](int t, int b) {
        const int base = t * TILE_E;
#pragma unroll
        for (int sub = 0; sub < 2; sub++) {
            int g = base + sub * 64 + se;
            int s = edge_index[g];
            int d = edge_index[NE + g];
            int idx = (sp < 2) ? d : s;
            const half* srcp = g_p + (size_t)idx * 128 + sp * 32;
            unsigned dp = sP_s + (unsigned)((b * 2 + sub) * SP_BYTES)
                        + (unsigned)((se * PAD_P + sp * 32) * 2);
#pragma unroll
            for (int j = 0; j < 4; j++) cpasync16(dp + j * 16, srcp + j * 8);
        }
        asm volatile("cp.async.commit_group;");
        if (tid < 128) {
            int s2 = edge_index[base + tid];
            int d2 = edge_index[NE + base + tid];
            sDst[b * 128 + tid] = d2;
            float dx = x[d2 * 3 + 0] - x[s2 * 3 + 0];
            float dy = x[d2 * 3 + 1] - x[s2 * 3 + 1];
            float dz = x[d2 * 3 + 2] - x[s2 * 3 + 2];
            float dd = dx * dx + dy * dy + dz * dz;
            sDis[b * 128 + tid] = fast_sigmoid(30.0f / (sqrtf(dd) + 1e-8f));
            sE[b * 128 + tid] = binf0;
        }
    };

    const int ntiles = NE / TILE_E;
    int t = blockIdx.x;
    if (t < ntiles) prefetch(t, 0);
    int buf = 0;

    for (; t < ntiles; t += gridDim.x, buf ^= 1) {
        asm volatile("cp.async.wait_group 0;");
        __syncthreads();   // sP[buf][*] + scalars[buf] visible; prev scatter done

        {
            int tn = t + gridDim.x;
            if (tn < ntiles) prefetch(tn, buf ^ 1);
        }

        float macc[2][2][2][4];   // [sub][mt][nt][4]
#pragma unroll
        for (int sub = 0; sub < 2; sub++) {
            const unsigned pb = sP_s + (unsigned)((buf * 2 + sub) * SP_BYTES) + poff_l;
#pragma unroll
            for (int mt = 0; mt < 2; mt++)
#pragma unroll
                for (int nt = 0; nt < 2; nt++) {
                    macc[sub][mt][nt][0] = bias2[nt][0]; macc[sub][mt][nt][1] = bias2[nt][1];
                    macc[sub][mt][nt][2] = bias2[nt][0]; macc[sub][mt][nt][3] = bias2[nt][1];
                }
#pragma unroll
            for (int kt = 0; kt < 4; kt++) {
#pragma unroll
                for (int mt = 0; mt < 2; mt++) {
                    unsigned p1[4], p2[4], a[4];
                    unsigned ab = pb + (mt * 16 * PAD_P + kt * 16) * 2;
                    ldmx4(p1, ab);
                    ldmx4(p2, ab + 128);
                    a[0] = hrelu2u(hadd2u(hadd2u(p1[0], p2[0]), bias1u[kt][0]));
                    a[1] = hrelu2u(hadd2u(hadd2u(p1[1], p2[1]), bias1u[kt][0]));
                    a[2] = hrelu2u(hadd2u(hadd2u(p1[2], p2[2]), bias1u[kt][1]));
                    a[3] = hrelu2u(hadd2u(hadd2u(p1[3], p2[3]), bias1u[kt][1]));
                    mma_f16(macc[sub][mt][0], a, wb2[kt][0]);
                    mma_f16(macc[sub][mt][1], a, wb2[kt][1]);
                }
            }

            float* sEs = sE + buf * 128 + sub * 64;
#pragma unroll
            for (int mt = 0; mt < 2; mt++) {
                int r = wm * 32 + mt * 16 + laned4;
                float plo = 0.0f, phi = 0.0f;
#pragma unroll
                for (int nt = 0; nt < 2; nt++) {
                    macc[sub][mt][nt][0] = fmaxf(macc[sub][mt][nt][0], 0.0f);
                    macc[sub][mt][nt][1] = fmaxf(macc[sub][mt][nt][1], 0.0f);
                    macc[sub][mt][nt][2] = fmaxf(macc[sub][mt][nt][2], 0.0f);
                    macc[sub][mt][nt][3] = fmaxf(macc[sub][mt][nt][3], 0.0f);
                    plo += macc[sub][mt][nt][0] * wf[nt][0] + macc[sub][mt][nt][1] * wf[nt][1];
                    phi += macc[sub][mt][nt][2] * wf[nt][0] + macc[sub][mt][nt][3] * wf[nt][1];
                }
                plo += __shfl_xor_sync(0xffffffffu, plo, 1);
                plo += __shfl_xor_sync(0xffffffffu, plo, 2);
                phi += __shfl_xor_sync(0xffffffffu, phi, 1);
                phi += __shfl_xor_sync(0xffffffffu, phi, 2);
                if (lane4 == 0) {
                    atomicAdd(&sEs[r], plo);
                    atomicAdd(&sEs[r + 8], phi);
                }
            }
        }
        __syncthreads();   // both subs' sE complete

        // ---- gate + v4 scatter (quad-pair exchange halves atomic op count) ----
#pragma unroll
        for (int sub = 0; sub < 2; sub++) {
            float* sEs = sE + buf * 128 + sub * 64;
            float* sDs = sDis + buf * 128 + sub * 64;
            int*   sDt = sDst + buf * 128 + sub * 64;
#pragma unroll
            for (int mt = 0; mt < 2; mt++) {
                int r = wm * 32 + mt * 16 + laned4;
                float w1 = fast_sigmoid(sEs[r] * sDs[r]);
                float w2 = fast_sigmoid(sEs[r + 8] * sDs[r + 8]);
                float* pr  = g_mi + (size_t)sDt[r] * H;
                float* pr8 = g_mi + (size_t)sDt[r + 8] * H;
#pragma unroll
                for (int nt = 0; nt < 2; nt++) {
                    int c = wn * 16 + nt * 8 + 2 * lane4;
                    float v0 = macc[sub][mt][nt][0] * w1, v1 = macc[sub][mt][nt][1] * w1;
                    float v2 = macc[sub][mt][nt][2] * w2, v3 = macc[sub][mt][nt][3] * w2;
                    float e0 = __shfl_xor_sync(0xffffffffu, v0, 1);
                    float e1 = __shfl_xor_sync(0xffffffffu, v1, 1);
                    float e2 = __shfl_xor_sync(0xffffffffu, v2, 1);
                    float e3 = __shfl_xor_sync(0xffffffffu, v3, 1);
                    if ((lane4 & 1) == 0) {
                        asm volatile("red.global.add.v4.f32 [%0], {%1,%2,%3,%4};"
                                     :: "l"(pr + c), "f"(v0), "f"(v1), "f"(e0), "f"(e1)
                                     : "memory");
                    } else {
                        asm volatile("red.global.add.v4.f32 [%0], {%1,%2,%3,%4};"
                                     :: "l"(pr8 + c - 2), "f"(e2), "f"(e3), "f"(v2), "f"(v3)
                                     : "memory");
                    }
                }
            }
        }
    }
}

// ---------------------------------------------------------------------------
// Node kernel: layer1 = relu(mi@Wn1_top + g_q)  (g_q has h-part + bias folded)
// ---------------------------------------------------------------------------
#define WARPS 8
#define EPT 8
#define NK_SMEM_FLOATS (4352 + 4352 + 192 + 8192 + 4096)
#define NK_SMEM_BYTES  (NK_SMEM_FLOATS * 4)

__global__ void __launch_bounds__(256, 2) node_kernel(
    const float* __restrict__ h,
    const float* __restrict__ Wn1,
    const float* __restrict__ Wn2, const float* __restrict__ bn2,
    const float* __restrict__ lng, const float* __restrict__ lnb,
    float* __restrict__ out)
{
    extern __shared__ float smem[];
    float* sW1 = smem;              // Wn1_top transposed [64][68]
    float* sW2 = sW1 + 64 * 68;     // Wn2 transposed [64][68]
    float* sB2 = sW2 + 64 * 68;
    float* sG  = sB2 + 64;
    float* sB  = sG + 64;
    float* sIn = sB + 64;           // 8*1024
    float* sT  = sIn + 8 * 1024;    // 8*512

    const int tid = threadIdx.x;
    for (int i = tid; i < 64 * 64; i += 256) {
        int k = i >> 6, c = i & 63;
        sW1[c * 68 + k] = Wn1[i];          // top half rows k<64
        sW2[c * 68 + k] = Wn2[i];
    }
    if (tid < 64) { sB2[tid] = bn2[tid]; sG[tid] = lng[tid]; sB[tid] = lnb[tid]; }
    __syncthreads();

    const int warp = tid >> 5, lane = tid & 31;
    const int c0 = lane, c1 = lane + 32;
    const float b2_0 = sB2[c0], b2_1 = sB2[c1];
    const float g0 = sG[c0], g1 = sG[c1];
    const float bb0 = sB[c0], bb1 = sB[c1];
    float* myIn = sIn + warp * 1024;
    float* myT  = sT + warp * 512;

    const int gw = blockIdx.x * WARPS + warp;
    const int nwarps = gridDim.x * WARPS;

    for (int base = gw * EPT; base < NN; base += nwarps * EPT) {
#pragma unroll
        for (int e = 0; e < EPT; e++) {
            const float* mip = g_mi + (size_t)(base + e) * H;
            const float* hp  = h + (size_t)(base + e) * H;
            *reinterpret_cast<float2*>(myIn + e * 128 + 2 * lane) =
                *reinterpret_cast<const float2*>(mip + 2 * lane);
            *reinterpret_cast<float2*>(myIn + e * 128 + 64 + 2 * lane) =
                *reinterpret_cast<const float2*>(hp + 2 * lane);
        }
        __syncwarp();

        // layer1: a = mi@Wn1_top + g_q   (g_q includes h-part + bn1)
        float a0[EPT], a1[EPT];
#pragma unroll
        for (int e = 0; e < EPT; e++) {
            const float* qp = g_q + (size_t)(base + e) * 64;
            a0[e] = qp[c0]; a1[e] = qp[c1];
        }
#pragma unroll 2
        for (int k = 0; k < 64; k += 4) {
            float4 w0 = *reinterpret_cast<const float4*>(sW1 + c0 * 68 + k);
            float4 w1 = *reinterpret_cast<const float4*>(sW1 + c1 * 68 + k);
#pragma unroll
            for (int e = 0; e < EPT; e++) {
                float4 v = *reinterpret_cast<const float4*>(myIn + e * 128 + k);
                a0[e] = fmaf(v.x, w0.x, a0[e]); a0[e] = fmaf(v.y, w0.y, a0[e]);
                a0[e] = fmaf(v.z, w0.z, a0[e]); a0[e] = fmaf(v.w, w0.w, a0[e]);
                a1[e] = fmaf(v.x, w1.x, a1[e]); a1[e] = fmaf(v.y, w1.y, a1[e]);
                a1[e] = fmaf(v.z, w1.z, a1[e]); a1[e] = fmaf(v.w, w1.w, a1[e]);
            }
        }
#pragma unroll
        for (int e = 0; e < EPT; e++) {
            myT[e * 64 + c0] = fmaxf(a0[e], 0.0f);
            myT[e * 64 + c1] = fmaxf(a1[e], 0.0f);
        }
        __syncwarp();

        float u0[EPT], u1[EPT];
#pragma unroll
        for (int e = 0; e < EPT; e++) { u0[e] = b2_0; u1[e] = b2_1; }
#pragma unroll 2
        for (int k = 0; k < 64; k += 4) {
            float4 w0 = *reinterpret_cast<const float4*>(sW2 + c0 * 68 + k);
            float4 w1 = *reinterpret_cast<const float4*>(sW2 + c1 * 68 + k);
#pragma unroll
            for (int e = 0; e < EPT; e++) {
                float4 v = *reinterpret_cast<const float4*>(myT + e * 64 + k);
                u0[e] = fmaf(v.x, w0.x, u0[e]); u0[e] = fmaf(v.y, w0.y, u0[e]);
                u0[e] = fmaf(v.z, w0.z, u0[e]); u0[e] = fmaf(v.w, w0.w, u0[e]);
                u1[e] = fmaf(v.x, w1.x, u1[e]); u1[e] = fmaf(v.y, w1.y, u1[e]);
                u1[e] = fmaf(v.z, w1.z, u1[e]); u1[e] = fmaf(v.w, w1.w, u1[e]);
            }
        }

#pragma unroll
        for (int e = 0; e < EPT; e++) {
            float z0 = u0[e] + myIn[e * 128 + 64 + c0];
            float z1 = u1[e] + myIn[e * 128 + 64 + c1];
            float s = z0 + z1;
            float q = z0 * z0 + z1 * z1;
#pragma unroll
            for (int o = 16; o > 0; o >>= 1) {
                s += __shfl_xor_sync(0xffffffffu, s, o);
                q += __shfl_xor_sync(0xffffffffu, q, o);
            }
            float mean = s * (1.0f / 64.0f);
            float var = q * (1.0f / 64.0f) - mean * mean;
            float inv = rsqrtf(var + 1e-5f);
            size_t ro = (size_t)(base + e) * H;
            out[ro + c0] = (z0 - mean) * inv * g0 + bb0;
            out[ro + c1] = (z1 - mean) * inv * g1 + bb1;
        }
        __syncwarp();
    }
}

__global__ void copy_x_kernel(const float4* __restrict__ x, float4* __restrict__ out)
{
    int i = blockIdx.x * blockDim.x + threadIdx.x;
    if (i < (NN * 3) / 4) out[i] = x[i];
}

extern "C" void kernel_launch(void* const* d_in, const int* in_sizes, int n_in,
                              void* d_out, int out_size)
{
    const float* h    = (const float*)d_in[0];
    const float* x    = (const float*)d_in[1];
    const int*   ei   = (const int*)d_in[2];
    const float* We1  = (const float*)d_in[3];
    const float* be1  = (const float*)d_in[4];
    const float* We2  = (const float*)d_in[5];
    const float* be2  = (const float*)d_in[6];
    const float* Winf = (const float*)d_in[7];
    const float* binf = (const float*)d_in[8];
    const float* Wn1  = (const float*)d_in[9];
    const float* bn1  = (const float*)d_in[10];
    const float* Wn2  = (const float*)d_in[11];
    const float* bn2  = (const float*)d_in[12];
    const float* lng  = (const float*)d_in[13];
    const float* lnb  = (const float*)d_in[14];
    float* out = (float*)d_out;

    void* mi_ptr = nullptr;
    cudaGetSymbolAddress(&mi_ptr, g_mi);
    cudaMemsetAsync(mi_ptr, 0, sizeof(float) * (size_t)NN * H, 0);
    precompute_kernel<<<(NN + 63) / 64, 256>>>(h, We1, Wn1, bn1);

    cudaFuncSetAttribute(edge_mma_kernel, cudaFuncAttributeMaxDynamicSharedMemorySize, EK_SMEM_BYTES);
    cudaFuncSetAttribute(node_kernel, cudaFuncAttributeMaxDynamicSharedMemorySize, NK_SMEM_BYTES);

    edge_mma_kernel<<<296, 256, EK_SMEM_BYTES>>>(x, ei, be1, We2, be2, Winf, binf);
    node_kernel<<<296, 256, NK_SMEM_BYTES>>>(h, Wn1, Wn2, bn2, lng, lnb, out);

    if (out_size >= NN * H + NN * 3) {
        copy_x_kernel<<<(NN * 3 / 4 + 255) / 256, 256>>>((const float4*)x,
                                                         (float4*)(out + (size_t)NN * H));
    }
}

// round 12
// speedup vs baseline: 1.0464x; 1.0464x over previous
#include <cuda_runtime.h>
#include <cuda_fp16.h>
#include <cstdint>

#define H 64
#define NN 100000
#define NE 1600000

// device-global scratch (no allocation allowed)
__device__ float g_mi[(size_t)NN * H];
__device__ half  g_p[(size_t)NN * 128];   // [P1 | P2] per node (edge MLP layer-1)
__device__ float g_q[(size_t)NN * 64];    // h@Wn1_bot + bn1 (node MLP layer-1 part)

__device__ __forceinline__ float fast_sigmoid(float z) {
    return 1.0f / (1.0f + __expf(-z));
}
__device__ __forceinline__ void mma_f16(float c[4], const unsigned a[4], const unsigned b[2]) {
    asm volatile("mma.sync.aligned.m16n8k16.row.col.f32.f16.f16.f32 "
        "{%0,%1,%2,%3}, {%4,%5,%6,%7}, {%8,%9}, {%0,%1,%2,%3};"
        : "+f"(c[0]), "+f"(c[1]), "+f"(c[2]), "+f"(c[3])
        : "r"(a[0]), "r"(a[1]), "r"(a[2]), "r"(a[3]), "r"(b[0]), "r"(b[1]));
}
__device__ __forceinline__ void ldmx4(unsigned a[4], unsigned saddr) {
    asm volatile("ldmatrix.sync.aligned.m8n8.x4.shared.b16 {%0,%1,%2,%3}, [%4];"
        : "=r"(a[0]), "=r"(a[1]), "=r"(a[2]), "=r"(a[3]) : "r"(saddr));
}
__device__ __forceinline__ unsigned h2u(half2 v) { return *reinterpret_cast<unsigned*>(&v); }
__device__ __forceinline__ void cpasync16(unsigned dst, const void* src) {
    asm volatile("cp.async.cg.shared.global [%0], [%1], 16;" :: "r"(dst), "l"(src));
}
__device__ __forceinline__ unsigned hadd2u(unsigned a, unsigned b) {
    unsigned r; asm("add.f16x2 %0, %1, %2;" : "=r"(r) : "r"(a), "r"(b)); return r;
}
__device__ __forceinline__ unsigned hrelu2u(unsigned a) {
    unsigned r; asm("max.f16x2 %0, %1, %2;" : "=r"(r) : "r"(a), "r"(0u)); return r;
}

// ---------------------------------------------------------------------------
// Precompute per node (64 nodes/block):
//   g_p[n][0:64]   = h[n] @ We1_top       (fp16)
//   g_p[n][64:128] = h[n] @ We1_bot       (fp16)
//   g_q[n][0:64]   = h[n] @ Wn1_bot + bn1 (fp32)
// ---------------------------------------------------------------------------
__global__ void __launch_bounds__(256) precompute_kernel(
    const float* __restrict__ h, const float* __restrict__ We1,
    const float* __restrict__ Wn1, const float* __restrict__ bn1)
{
    __shared__ half sAh[64 * 72];
    const int tid = threadIdx.x;
    const int warp = tid >> 5, lane = tid & 31;
    const int lane4 = lane & 3, laned4 = lane >> 2;
    const int wm = warp & 1, wn = warp >> 1;   // 32 rows x 48 out-cols per warp

    unsigned wb[4][6][2];
#pragma unroll
    for (int kt = 0; kt < 4; kt++)
#pragma unroll
        for (int nt = 0; nt < 6; nt++) {
            int j = wn * 48 + nt * 8 + laned4;      // 0..191 output col
            int k = kt * 16 + 2 * lane4;
            float w00, w01, w10, w11;
            if (j < 128) {
                int kr = k + ((j >= 64) ? 64 : 0);
                int jc = j & 63;
                w00 = We1[kr * 64 + jc];       w01 = We1[(kr + 1) * 64 + jc];
                w10 = We1[(kr + 8) * 64 + jc]; w11 = We1[(kr + 9) * 64 + jc];
            } else {
                int jc = j - 128;
                w00 = Wn1[(k + 64) * 64 + jc];     w01 = Wn1[(k + 65) * 64 + jc];
                w10 = Wn1[(k + 72) * 64 + jc];     w11 = Wn1[(k + 73) * 64 + jc];
            }
            wb[kt][nt][0] = h2u(__floats2half2_rn(w00, w01));
            wb[kt][nt][1] = h2u(__floats2half2_rn(w10, w11));
        }

    const int node0 = blockIdx.x * 64;
    {
        int nd = tid >> 2, q = tid & 3;
        if (node0 + nd < NN) {
            const float* src = h + (size_t)(node0 + nd) * H + q * 16;
            half* dst = sAh + nd * 72 + q * 16;
#pragma unroll
            for (int j = 0; j < 4; j++) {
                float4 v = *reinterpret_cast<const float4*>(src + j * 4);
                *reinterpret_cast<half2*>(dst + j * 4)     = __floats2half2_rn(v.x, v.y);
                *reinterpret_cast<half2*>(dst + j * 4 + 2) = __floats2half2_rn(v.z, v.w);
            }
        }
    }
    __syncthreads();

    const int al = lane & 15, ah = lane >> 4;
    unsigned abase = (unsigned)__cvta_generic_to_shared(sAh) + ((wm * 32 + al) * 72 + ah * 8) * 2;
    float acc[2][6][4] = {};
#pragma unroll
    for (int kt = 0; kt < 4; kt++)
#pragma unroll
        for (int mt = 0; mt < 2; mt++) {
            unsigned a[4];
            ldmx4(a, abase + (mt * 16 * 72 + kt * 16) * 2);
#pragma unroll
            for (int nt = 0; nt < 6; nt++)
                mma_f16(acc[mt][nt], a, wb[kt][nt]);
        }
#pragma unroll
    for (int mt = 0; mt < 2; mt++)
#pragma unroll
        for (int nt = 0; nt < 6; nt++) {
            int r = wm * 32 + mt * 16 + laned4;
            int c = wn * 48 + nt * 8 + 2 * lane4;
            if (c < 128) {
                if (node0 + r < NN)
                    *reinterpret_cast<half2*>(g_p + (size_t)(node0 + r) * 128 + c) =
                        __floats2half2_rn(acc[mt][nt][0], acc[mt][nt][1]);
                if (node0 + r + 8 < NN)
                    *reinterpret_cast<half2*>(g_p + (size_t)(node0 + r + 8) * 128 + c) =
                        __floats2half2_rn(acc[mt][nt][2], acc[mt][nt][3]);
            } else {
                int cq = c - 128;
                float b0 = bn1[cq], b1 = bn1[cq + 1];
                if (node0 + r < NN)
                    *reinterpret_cast<float2*>(g_q + (size_t)(node0 + r) * 64 + cq) =
                        make_float2(acc[mt][nt][0] + b0, acc[mt][nt][1] + b1);
                if (node0 + r + 8 < NN)
                    *reinterpret_cast<float2*>(g_q + (size_t)(node0 + r + 8) * 64 + cq) =
                        make_float2(acc[mt][nt][2] + b0, acc[mt][nt][3] + b1);
            }
        }
}

// ---------------------------------------------------------------------------
// Edge kernel: gather P1[dst],P2[src]; fused relu(P1+P2+b) -> GEMM2; v2 scatter
// ---------------------------------------------------------------------------
#define TILE_E 128        // 2 subtiles of 64
#define PAD_P 136         // halves/row (272B): conflict-free ldmatrix
#define SP_BYTES (64 * PAD_P * 2)
#define EK_SMEM_BYTES (4*SP_BYTES + 2*128*4*3)

__global__ void __launch_bounds__(256, 2) edge_mma_kernel(
    const float* __restrict__ x,
    const int* __restrict__ edge_index,
    const float* __restrict__ be1,
    const float* __restrict__ We2, const float* __restrict__ be2,
    const float* __restrict__ Winf, const float* __restrict__ binf)
{
    extern __shared__ char smraw[];
    half*  sP   = (half*)smraw;                      // [4][64][136]  (buf*2+sub)
    float* sDis = (float*)(sP + 4 * 64 * PAD_P);     // [2][128]
    float* sE   = sDis + 256;                        // [2][128]
    int*   sDst = (int*)(sE + 256);                  // [2][128]

    const int tid  = threadIdx.x;
    const int warp = tid >> 5, lane = tid & 31;
    const int lane4 = lane & 3, laned4 = lane >> 2;
    const int wm = warp & 1;       // rows 32*wm .. +32 (within subtile)
    const int wn = warp >> 1;      // cols 16*wn .. +16

    unsigned wb2[4][2][2];
#pragma unroll
    for (int kt = 0; kt < 4; kt++)
#pragma unroll
        for (int nt = 0; nt < 2; nt++) {
            int n = wn * 16 + nt * 8 + laned4;
            int k = kt * 16 + 2 * lane4;
            wb2[kt][nt][0] = h2u(__floats2half2_rn(We2[k * 64 + n], We2[(k + 1) * 64 + n]));
            wb2[kt][nt][1] = h2u(__floats2half2_rn(We2[(k + 8) * 64 + n], We2[(k + 9) * 64 + n]));
        }
    unsigned bias1u[4][2];
#pragma unroll
    for (int kt = 0; kt < 4; kt++) {
        int k = kt * 16 + 2 * lane4;
        bias1u[kt][0] = h2u(__floats2half2_rn(be1[k], be1[k + 1]));
        bias1u[kt][1] = h2u(__floats2half2_rn(be1[k + 8], be1[k + 9]));
    }
    float bias2[2][2], wf[2][2];
#pragma unroll
    for (int nt = 0; nt < 2; nt++) {
        int c = wn * 16 + nt * 8 + 2 * lane4;
        bias2[nt][0] = be2[c]; bias2[nt][1] = be2[c + 1];
        wf[nt][0]    = Winf[c]; wf[nt][1]   = Winf[c + 1];
    }
    const float binf0 = binf[0];

    unsigned sP_s = (unsigned)__cvta_generic_to_shared(sP);
    const int al = lane & 15, ah = lane >> 4;
    const unsigned poff_l = (unsigned)(((wm * 32 + al) * PAD_P + ah * 8) * 2);

    const int se = tid >> 2;
    const int sp = tid & 3;

    auto prefetch = [&](int t, int b) {
        const int base = t * TILE_E;
#pragma unroll
        for (int sub = 0; sub < 2; sub++) {
            int g = base + sub * 64 + se;
            int s = edge_index[g];
            int d = edge_index[NE + g];
            int idx = (sp < 2) ? d : s;
            const half* srcp = g_p + (size_t)idx * 128 + sp * 32;
            unsigned dp = sP_s + (unsigned)((b * 2 + sub) * SP_BYTES)
                        + (unsigned)((se * PAD_P + sp * 32) * 2);
#pragma unroll
            for (int j = 0; j < 4; j++) cpasync16(dp + j * 16, srcp + j * 8);
        }
        asm volatile("cp.async.commit_group;");
        if (tid < 128) {
            int s2 = edge_index[base + tid];
            int d2 = edge_index[NE + base + tid];
            sDst[b * 128 + tid] = d2;
            float dx = x[d2 * 3 + 0] - x[s2 * 3 + 0];
            float dy = x[d2 * 3 + 1] - x[s2 * 3 + 1];
            float dz = x[d2 * 3 + 2] - x[s2 * 3 + 2];
            float dd = dx * dx + dy * dy + dz * dz;
            sDis[b * 128 + tid] = fast_sigmoid(30.0f / (sqrtf(dd) + 1e-8f));
            sE[b * 128 + tid] = binf0;
        }
    };

    const int ntiles = NE / TILE_E;
    int t = blockIdx.x;
    if (t < ntiles) prefetch(t, 0);
    int buf = 0;

    for (; t < ntiles; t += gridDim.x, buf ^= 1) {
        asm volatile("cp.async.wait_group 0;");
        __syncthreads();   // sP[buf][*] + scalars[buf] visible; prev scatter done

        {
            int tn = t + gridDim.x;
            if (tn < ntiles) prefetch(tn, buf ^ 1);
        }

        float macc[2][2][2][4];   // [sub][mt][nt][4]
#pragma unroll
        for (int sub = 0; sub < 2; sub++) {
            const unsigned pb = sP_s + (unsigned)((buf * 2 + sub) * SP_BYTES) + poff_l;
#pragma unroll
            for (int mt = 0; mt < 2; mt++)
#pragma unroll
                for (int nt = 0; nt < 2; nt++) {
                    macc[sub][mt][nt][0] = bias2[nt][0]; macc[sub][mt][nt][1] = bias2[nt][1];
                    macc[sub][mt][nt][2] = bias2[nt][0]; macc[sub][mt][nt][3] = bias2[nt][1];
                }
#pragma unroll
            for (int kt = 0; kt < 4; kt++) {
#pragma unroll
                for (int mt = 0; mt < 2; mt++) {
                    unsigned p1[4], p2[4], a[4];
                    unsigned ab = pb + (mt * 16 * PAD_P + kt * 16) * 2;
                    ldmx4(p1, ab);
                    ldmx4(p2, ab + 128);
                    a[0] = hrelu2u(hadd2u(hadd2u(p1[0], p2[0]), bias1u[kt][0]));
                    a[1] = hrelu2u(hadd2u(hadd2u(p1[1], p2[1]), bias1u[kt][0]));
                    a[2] = hrelu2u(hadd2u(hadd2u(p1[2], p2[2]), bias1u[kt][1]));
                    a[3] = hrelu2u(hadd2u(hadd2u(p1[3], p2[3]), bias1u[kt][1]));
                    mma_f16(macc[sub][mt][0], a, wb2[kt][0]);
                    mma_f16(macc[sub][mt][1], a, wb2[kt][1]);
                }
            }

            float* sEs = sE + buf * 128 + sub * 64;
#pragma unroll
            for (int mt = 0; mt < 2; mt++) {
                int r = wm * 32 + mt * 16 + laned4;
                float plo = 0.0f, phi = 0.0f;
#pragma unroll
                for (int nt = 0; nt < 2; nt++) {
                    macc[sub][mt][nt][0] = fmaxf(macc[sub][mt][nt][0], 0.0f);
                    macc[sub][mt][nt][1] = fmaxf(macc[sub][mt][nt][1], 0.0f);
                    macc[sub][mt][nt][2] = fmaxf(macc[sub][mt][nt][2], 0.0f);
                    macc[sub][mt][nt][3] = fmaxf(macc[sub][mt][nt][3], 0.0f);
                    plo += macc[sub][mt][nt][0] * wf[nt][0] + macc[sub][mt][nt][1] * wf[nt][1];
                    phi += macc[sub][mt][nt][2] * wf[nt][0] + macc[sub][mt][nt][3] * wf[nt][1];
                }
                plo += __shfl_xor_sync(0xffffffffu, plo, 1);
                plo += __shfl_xor_sync(0xffffffffu, plo, 2);
                phi += __shfl_xor_sync(0xffffffffu, phi, 1);
                phi += __shfl_xor_sync(0xffffffffu, phi, 2);
                if (lane4 == 0) {
                    atomicAdd(&sEs[r], plo);
                    atomicAdd(&sEs[r + 8], phi);
                }
            }
        }
        __syncthreads();   // both subs' sE complete

        // ---- gate + direct v2 scatter from registers (straight-line) ----
#pragma unroll
        for (int sub = 0; sub < 2; sub++) {
            float* sEs = sE + buf * 128 + sub * 64;
            float* sDs = sDis + buf * 128 + sub * 64;
            int*   sDt = sDst + buf * 128 + sub * 64;
#pragma unroll
            for (int mt = 0; mt < 2; mt++) {
                int r = wm * 32 + mt * 16 + laned4;
                float w1 = fast_sigmoid(sEs[r] * sDs[r]);
                float w2 = fast_sigmoid(sEs[r + 8] * sDs[r + 8]);
                float* p1 = g_mi + (size_t)sDt[r] * H;
                float* p2 = g_mi + (size_t)sDt[r + 8] * H;
#pragma unroll
                for (int nt = 0; nt < 2; nt++) {
                    int c = wn * 16 + nt * 8 + 2 * lane4;
                    asm volatile("red.global.add.v2.f32 [%0], {%1,%2};"
                                 :: "l"(p1 + c), "f"(macc[sub][mt][nt][0] * w1), "f"(macc[sub][mt][nt][1] * w1)
                                 : "memory");
                    asm volatile("red.global.add.v2.f32 [%0], {%1,%2};"
                                 :: "l"(p2 + c), "f"(macc[sub][mt][nt][2] * w2), "f"(macc[sub][mt][nt][3] * w2)
                                 : "memory");
                }
            }
        }
    }
}

// ---------------------------------------------------------------------------
// Node kernel: layer1 = relu(mi@Wn1_top + g_q)  (g_q has h-part + bn1 folded)
// ---------------------------------------------------------------------------
#define WARPS 8
#define EPT 8
#define NK_SMEM_FLOATS (4352 + 4352 + 192 + 8192 + 4096)
#define NK_SMEM_BYTES  (NK_SMEM_FLOATS * 4)

__global__ void __launch_bounds__(256, 2) node_kernel(
    const float* __restrict__ h,
    const float* __restrict__ Wn1,
    const float* __restrict__ Wn2, const float* __restrict__ bn2,
    const float* __restrict__ lng, const float* __restrict__ lnb,
    float* __restrict__ out)
{
    extern __shared__ float smem[];
    float* sW1 = smem;              // Wn1_top transposed [64][68]
    float* sW2 = sW1 + 64 * 68;     // Wn2 transposed [64][68]
    float* sB2 = sW2 + 64 * 68;
    float* sG  = sB2 + 64;
    float* sB  = sG + 64;
    float* sIn = sB + 64;           // 8*1024
    float* sT  = sIn + 8 * 1024;    // 8*512

    const int tid = threadIdx.x;
    for (int i = tid; i < 64 * 64; i += 256) {
        int k = i >> 6, c = i & 63;
        sW1[c * 68 + k] = Wn1[i];          // top half rows k<64
        sW2[c * 68 + k] = Wn2[i];
    }
    if (tid < 64) { sB2[tid] = bn2[tid]; sG[tid] = lng[tid]; sB[tid] = lnb[tid]; }
    __syncthreads();

    const int warp = tid >> 5, lane = tid & 31;
    const int c0 = lane, c1 = lane + 32;
    const float b2_0 = sB2[c0], b2_1 = sB2[c1];
    const float g0 = sG[c0], g1 = sG[c1];
    const float bb0 = sB[c0], bb1 = sB[c1];
    float* myIn = sIn + warp * 1024;
    float* myT  = sT + warp * 512;

    const int gw = blockIdx.x * WARPS + warp;
    const int nwarps = gridDim.x * WARPS;

    for (int base = gw * EPT; base < NN; base += nwarps * EPT) {
#pragma unroll
        for (int e = 0; e < EPT; e++) {
            const float* mip = g_mi + (size_t)(base + e) * H;
            const float* hp  = h + (size_t)(base + e) * H;
            *reinterpret_cast<float2*>(myIn + e * 128 + 2 * lane) =
                *reinterpret_cast<const float2*>(mip + 2 * lane);
            *reinterpret_cast<float2*>(myIn + e * 128 + 64 + 2 * lane) =
                *reinterpret_cast<const float2*>(hp + 2 * lane);
        }
        __syncwarp();

        // layer1: a = mi@Wn1_top + g_q   (g_q includes h-part + bn1)
        float a0[EPT], a1[EPT];
#pragma unroll
        for (int e = 0; e < EPT; e++) {
            const float* qp = g_q + (size_t)(base + e) * 64;
            a0[e] = qp[c0]; a1[e] = qp[c1];
        }
#pragma unroll 2
        for (int k = 0; k < 64; k += 4) {
            float4 w0 = *reinterpret_cast<const float4*>(sW1 + c0 * 68 + k);
            float4 w1 = *reinterpret_cast<const float4*>(sW1 + c1 * 68 + k);
#pragma unroll
            for (int e = 0; e < EPT; e++) {
                float4 v = *reinterpret_cast<const float4*>(myIn + e * 128 + k);
                a0[e] = fmaf(v.x, w0.x, a0[e]); a0[e] = fmaf(v.y, w0.y, a0[e]);
                a0[e] = fmaf(v.z, w0.z, a0[e]); a0[e] = fmaf(v.w, w0.w, a0[e]);
                a1[e] = fmaf(v.x, w1.x, a1[e]); a1[e] = fmaf(v.y, w1.y, a1[e]);
                a1[e] = fmaf(v.z, w1.z, a1[e]); a1[e] = fmaf(v.w, w1.w, a1[e]);
            }
        }
#pragma unroll
        for (int e = 0; e < EPT; e++) {
            myT[e * 64 + c0] = fmaxf(a0[e], 0.0f);
            myT[e * 64 + c1] = fmaxf(a1[e], 0.0f);
        }
        __syncwarp();

        float u0[EPT], u1[EPT];
#pragma unroll
        for (int e = 0; e < EPT; e++) { u0[e] = b2_0; u1[e] = b2_1; }
#pragma unroll 2
        for (int k = 0; k < 64; k += 4) {
            float4 w0 = *reinterpret_cast<const float4*>(sW2 + c0 * 68 + k);
            float4 w1 = *reinterpret_cast<const float4*>(sW2 + c1 * 68 + k);
#pragma unroll
            for (int e = 0; e < EPT; e++) {
                float4 v = *reinterpret_cast<const float4*>(myT + e * 64 + k);
                u0[e] = fmaf(v.x, w0.x, u0[e]); u0[e] = fmaf(v.y, w0.y, u0[e]);
                u0[e] = fmaf(v.z, w0.z, u0[e]); u0[e] = fmaf(v.w, w0.w, u0[e]);
                u1[e] = fmaf(v.x, w1.x, u1[e]); u1[e] = fmaf(v.y, w1.y, u1[e]);
                u1[e] = fmaf(v.z, w1.z, u1[e]); u1[e] = fmaf(v.w, w1.w, u1[e]);
            }
        }

#pragma unroll
        for (int e = 0; e < EPT; e++) {
            float z0 = u0[e] + myIn[e * 128 + 64 + c0];
            float z1 = u1[e] + myIn[e * 128 + 64 + c1];
            float s = z0 + z1;
            float q = z0 * z0 + z1 * z1;
#pragma unroll
            for (int o = 16; o > 0; o >>= 1) {
                s += __shfl_xor_sync(0xffffffffu, s, o);
                q += __shfl_xor_sync(0xffffffffu, q, o);
            }
            float mean = s * (1.0f / 64.0f);
            float var = q * (1.0f / 64.0f) - mean * mean;
            float inv = rsqrtf(var + 1e-5f);
            size_t ro = (size_t)(base + e) * H;
            out[ro + c0] = (z0 - mean) * inv * g0 + bb0;
            out[ro + c1] = (z1 - mean) * inv * g1 + bb1;
        }
        __syncwarp();
    }
}

__global__ void copy_x_kernel(const float4* __restrict__ x, float4* __restrict__ out)
{
    int i = blockIdx.x * blockDim.x + threadIdx.x;
    if (i < (NN * 3) / 4) out[i] = x[i];
}

extern "C" void kernel_launch(void* const* d_in, const int* in_sizes, int n_in,
                              void* d_out, int out_size)
{
    const float* h    = (const float*)d_in[0];
    const float* x    = (const float*)d_in[1];
    const int*   ei   = (const int*)d_in[2];
    const float* We1  = (const float*)d_in[3];
    const float* be1  = (const float*)d_in[4];
    const float* We2  = (const float*)d_in[5];
    const float* be2  = (const float*)d_in[6];
    const float* Winf = (const float*)d_in[7];
    const float* binf = (const float*)d_in[8];
    const float* Wn1  = (const float*)d_in[9];
    const float* bn1  = (const float*)d_in[10];
    const float* Wn2  = (const float*)d_in[11];
    const float* bn2  = (const float*)d_in[12];
    const float* lng  = (const float*)d_in[13];
    const float* lnb  = (const float*)d_in[14];
    float* out = (float*)d_out;

    void* mi_ptr = nullptr;
    cudaGetSymbolAddress(&mi_ptr, g_mi);
    cudaMemsetAsync(mi_ptr, 0, sizeof(float) * (size_t)NN * H, 0);
    precompute_kernel<<<(NN + 63) / 64, 256>>>(h, We1, Wn1, bn1);

    cudaFuncSetAttribute(edge_mma_kernel, cudaFuncAttributeMaxDynamicSharedMemorySize, EK_SMEM_BYTES);
    cudaFuncSetAttribute(node_kernel, cudaFuncAttributeMaxDynamicSharedMemorySize, NK_SMEM_BYTES);

    edge_mma_kernel<<<296, 256, EK_SMEM_BYTES>>>(x, ei, be1, We2, be2, Winf, binf);
    node_kernel<<<296, 256, NK_SMEM_BYTES>>>(h, Wn1, Wn2, bn2, lng, lnb, out);

    if (out_size >= NN * H + NN * 3) {
        copy_x_kernel<<<(NN * 3 / 4 + 255) / 256, 256>>>((const float4*)x,
                                                         (float4*)(out + (size_t)NN * H));
    }
}

// round 13
// speedup vs baseline: 1.1394x; 1.0889x over previous
#include <cuda_runtime.h>
#include <cuda_fp16.h>
#include <cstdint>

#define H 64
#define NN 100000
#define NE 1600000

// device-global scratch (no allocation allowed)
__device__ half  g_mi16[(size_t)NN * H];  // fp16 segment-sum accumulator
__device__ half  g_p[(size_t)NN * 128];   // [P1 | P2] per node (edge MLP layer-1)
__device__ float g_q[(size_t)NN * 64];    // h@Wn1_bot + bn1 (node MLP layer-1 part)

__device__ __forceinline__ float fast_sigmoid(float z) {
    return 1.0f / (1.0f + __expf(-z));
}
__device__ __forceinline__ void mma_f16(float c[4], const unsigned a[4], const unsigned b[2]) {
    asm volatile("mma.sync.aligned.m16n8k16.row.col.f32.f16.f16.f32 "
        "{%0,%1,%2,%3}, {%4,%5,%6,%7}, {%8,%9}, {%0,%1,%2,%3};"
        : "+f"(c[0]), "+f"(c[1]), "+f"(c[2]), "+f"(c[3])
        : "r"(a[0]), "r"(a[1]), "r"(a[2]), "r"(a[3]), "r"(b[0]), "r"(b[1]));
}
__device__ __forceinline__ void ldmx4(unsigned a[4], unsigned saddr) {
    asm volatile("ldmatrix.sync.aligned.m8n8.x4.shared.b16 {%0,%1,%2,%3}, [%4];"
        : "=r"(a[0]), "=r"(a[1]), "=r"(a[2]), "=r"(a[3]) : "r"(saddr));
}
__device__ __forceinline__ unsigned h2u(half2 v) { return *reinterpret_cast<unsigned*>(&v); }
__device__ __forceinline__ void cpasync16(unsigned dst, const void* src) {
    asm volatile("cp.async.cg.shared.global [%0], [%1], 16;" :: "r"(dst), "l"(src));
}
__device__ __forceinline__ unsigned hadd2u(unsigned a, unsigned b) {
    unsigned r; asm("add.f16x2 %0, %1, %2;" : "=r"(r) : "r"(a), "r"(b)); return r;
}
__device__ __forceinline__ unsigned hrelu2u(unsigned a) {
    unsigned r; asm("max.f16x2 %0, %1, %2;" : "=r"(r) : "r"(a), "r"(0u)); return r;
}
__device__ __forceinline__ void red_f16x2(half* p, float lo, float hi) {
    unsigned v = h2u(__floats2half2_rn(lo, hi));
    asm volatile("red.global.add.noftz.f16x2 [%0], %1;" :: "l"(p), "r"(v) : "memory");
}

// ---------------------------------------------------------------------------
// Precompute per node (64 nodes/block):
//   g_p[n][0:64]   = h[n] @ We1_top       (fp16)
//   g_p[n][64:128] = h[n] @ We1_bot       (fp16)
//   g_q[n][0:64]   = h[n] @ Wn1_bot + bn1 (fp32)
// ---------------------------------------------------------------------------
__global__ void __launch_bounds__(256) precompute_kernel(
    const float* __restrict__ h, const float* __restrict__ We1,
    const float* __restrict__ Wn1, const float* __restrict__ bn1)
{
    __shared__ half sAh[64 * 72];
    const int tid = threadIdx.x;
    const int warp = tid >> 5, lane = tid & 31;
    const int lane4 = lane & 3, laned4 = lane >> 2;
    const int wm = warp & 1, wn = warp >> 1;   // 32 rows x 48 out-cols per warp

    unsigned wb[4][6][2];
#pragma unroll
    for (int kt = 0; kt < 4; kt++)
#pragma unroll
        for (int nt = 0; nt < 6; nt++) {
            int j = wn * 48 + nt * 8 + laned4;      // 0..191 output col
            int k = kt * 16 + 2 * lane4;
            float w00, w01, w10, w11;
            if (j < 128) {
                int kr = k + ((j >= 64) ? 64 : 0);
                int jc = j & 63;
                w00 = We1[kr * 64 + jc];       w01 = We1[(kr + 1) * 64 + jc];
                w10 = We1[(kr + 8) * 64 + jc]; w11 = We1[(kr + 9) * 64 + jc];
            } else {
                int jc = j - 128;
                w00 = Wn1[(k + 64) * 64 + jc];     w01 = Wn1[(k + 65) * 64 + jc];
                w10 = Wn1[(k + 72) * 64 + jc];     w11 = Wn1[(k + 73) * 64 + jc];
            }
            wb[kt][nt][0] = h2u(__floats2half2_rn(w00, w01));
            wb[kt][nt][1] = h2u(__floats2half2_rn(w10, w11));
        }

    const int node0 = blockIdx.x * 64;
    {
        int nd = tid >> 2, q = tid & 3;
        if (node0 + nd < NN) {
            const float* src = h + (size_t)(node0 + nd) * H + q * 16;
            half* dst = sAh + nd * 72 + q * 16;
#pragma unroll
            for (int j = 0; j < 4; j++) {
                float4 v = *reinterpret_cast<const float4*>(src + j * 4);
                *reinterpret_cast<half2*>(dst + j * 4)     = __floats2half2_rn(v.x, v.y);
                *reinterpret_cast<half2*>(dst + j * 4 + 2) = __floats2half2_rn(v.z, v.w);
            }
        }
    }
    __syncthreads();

    const int al = lane & 15, ah = lane >> 4;
    unsigned abase = (unsigned)__cvta_generic_to_shared(sAh) + ((wm * 32 + al) * 72 + ah * 8) * 2;
    float acc[2][6][4] = {};
#pragma unroll
    for (int kt = 0; kt < 4; kt++)
#pragma unroll
        for (int mt = 0; mt < 2; mt++) {
            unsigned a[4];
            ldmx4(a, abase + (mt * 16 * 72 + kt * 16) * 2);
#pragma unroll
            for (int nt = 0; nt < 6; nt++)
                mma_f16(acc[mt][nt], a, wb[kt][nt]);
        }
#pragma unroll
    for (int mt = 0; mt < 2; mt++)
#pragma unroll
        for (int nt = 0; nt < 6; nt++) {
            int r = wm * 32 + mt * 16 + laned4;
            int c = wn * 48 + nt * 8 + 2 * lane4;
            if (c < 128) {
                if (node0 + r < NN)
                    *reinterpret_cast<half2*>(g_p + (size_t)(node0 + r) * 128 + c) =
                        __floats2half2_rn(acc[mt][nt][0], acc[mt][nt][1]);
                if (node0 + r + 8 < NN)
                    *reinterpret_cast<half2*>(g_p + (size_t)(node0 + r + 8) * 128 + c) =
                        __floats2half2_rn(acc[mt][nt][2], acc[mt][nt][3]);
            } else {
                int cq = c - 128;
                float b0 = bn1[cq], b1 = bn1[cq + 1];
                if (node0 + r < NN)
                    *reinterpret_cast<float2*>(g_q + (size_t)(node0 + r) * 64 + cq) =
                        make_float2(acc[mt][nt][0] + b0, acc[mt][nt][1] + b1);
                if (node0 + r + 8 < NN)
                    *reinterpret_cast<float2*>(g_q + (size_t)(node0 + r + 8) * 64 + cq) =
                        make_float2(acc[mt][nt][2] + b0, acc[mt][nt][3] + b1);
            }
        }
}

// ---------------------------------------------------------------------------
// Edge kernel: gather P1[dst],P2[src]; fused relu(P1+P2+b) -> GEMM2;
// fp16x2 atomic scatter (half the bytes of v2.f32, same op count)
// ---------------------------------------------------------------------------
#define TILE_E 128        // 2 subtiles of 64
#define PAD_P 136         // halves/row (272B): conflict-free ldmatrix
#define SP_BYTES (64 * PAD_P * 2)
#define EK_SMEM_BYTES (4*SP_BYTES + 2*128*4*3)

__global__ void __launch_bounds__(256, 2) edge_mma_kernel(
    const float* __restrict__ x,
    const int* __restrict__ edge_index,
    const float* __restrict__ be1,
    const float* __restrict__ We2, const float* __restrict__ be2,
    const float* __restrict__ Winf, const float* __restrict__ binf)
{
    extern __shared__ char smraw[];
    half*  sP   = (half*)smraw;                      // [4][64][136]  (buf*2+sub)
    float* sDis = (float*)(sP + 4 * 64 * PAD_P);     // [2][128]
    float* sE   = sDis + 256;                        // [2][128]
    int*   sDst = (int*)(sE + 256);                  // [2][128]

    const int tid  = threadIdx.x;
    const int warp = tid >> 5, lane = tid & 31;
    const int lane4 = lane & 3, laned4 = lane >> 2;
    const int wm = warp & 1;       // rows 32*wm .. +32 (within subtile)
    const int wn = warp >> 1;      // cols 16*wn .. +16

    unsigned wb2[4][2][2];
#pragma unroll
    for (int kt = 0; kt < 4; kt++)
#pragma unroll
        for (int nt = 0; nt < 2; nt++) {
            int n = wn * 16 + nt * 8 + laned4;
            int k = kt * 16 + 2 * lane4;
            wb2[kt][nt][0] = h2u(__floats2half2_rn(We2[k * 64 + n], We2[(k + 1) * 64 + n]));
            wb2[kt][nt][1] = h2u(__floats2half2_rn(We2[(k + 8) * 64 + n], We2[(k + 9) * 64 + n]));
        }
    unsigned bias1u[4][2];
#pragma unroll
    for (int kt = 0; kt < 4; kt++) {
        int k = kt * 16 + 2 * lane4;
        bias1u[kt][0] = h2u(__floats2half2_rn(be1[k], be1[k + 1]));
        bias1u[kt][1] = h2u(__floats2half2_rn(be1[k + 8], be1[k + 9]));
    }
    float bias2[2][2], wf[2][2];
#pragma unroll
    for (int nt = 0; nt < 2; nt++) {
        int c = wn * 16 + nt * 8 + 2 * lane4;
        bias2[nt][0] = be2[c]; bias2[nt][1] = be2[c + 1];
        wf[nt][0]    = Winf[c]; wf[nt][1]   = Winf[c + 1];
    }
    const float binf0 = binf[0];

    unsigned sP_s = (unsigned)__cvta_generic_to_shared(sP);
    const int al = lane & 15, ah = lane >> 4;
    const unsigned poff_l = (unsigned)(((wm * 32 + al) * PAD_P + ah * 8) * 2);

    const int se = tid >> 2;
    const int sp = tid & 3;

    auto prefetch = [&](int t, int b) {
        const int base = t * TILE_E;
#pragma unroll
        for (int sub = 0; sub < 2; sub++) {
            int g = base + sub * 64 + se;
            int s = edge_index[g];
            int d = edge_index[NE + g];
            int idx = (sp < 2) ? d : s;
            const half* srcp = g_p + (size_t)idx * 128 + sp * 32;
            unsigned dp = sP_s + (unsigned)((b * 2 + sub) * SP_BYTES)
                        + (unsigned)((se * PAD_P + sp * 32) * 2);
#pragma unroll
            for (int j = 0; j < 4; j++) cpasync16(dp + j * 16, srcp + j * 8);
        }
        asm volatile("cp.async.commit_group;");
        if (tid < 128) {
            int s2 = edge_index[base + tid];
            int d2 = edge_index[NE + base + tid];
            sDst[b * 128 + tid] = d2;
            float dx = x[d2 * 3 + 0] - x[s2 * 3 + 0];
            float dy = x[d2 * 3 + 1] - x[s2 * 3 + 1];
            float dz = x[d2 * 3 + 2] - x[s2 * 3 + 2];
            float dd = dx * dx + dy * dy + dz * dz;
            sDis[b * 128 + tid] = fast_sigmoid(30.0f / (sqrtf(dd) + 1e-8f));
            sE[b * 128 + tid] = binf0;
        }
    };

    const int ntiles = NE / TILE_E;
    int t = blockIdx.x;
    if (t < ntiles) prefetch(t, 0);
    int buf = 0;

    for (; t < ntiles; t += gridDim.x, buf ^= 1) {
        asm volatile("cp.async.wait_group 0;");
        __syncthreads();   // sP[buf][*] + scalars[buf] visible; prev scatter done

        {
            int tn = t + gridDim.x;
            if (tn < ntiles) prefetch(tn, buf ^ 1);
        }

        float macc[2][2][2][4];   // [sub][mt][nt][4]
#pragma unroll
        for (int sub = 0; sub < 2; sub++) {
            const unsigned pb = sP_s + (unsigned)((buf * 2 + sub) * SP_BYTES) + poff_l;
#pragma unroll
            for (int mt = 0; mt < 2; mt++)
#pragma unroll
                for (int nt = 0; nt < 2; nt++) {
                    macc[sub][mt][nt][0] = bias2[nt][0]; macc[sub][mt][nt][1] = bias2[nt][1];
                    macc[sub][mt][nt][2] = bias2[nt][0]; macc[sub][mt][nt][3] = bias2[nt][1];
                }
#pragma unroll
            for (int kt = 0; kt < 4; kt++) {
#pragma unroll
                for (int mt = 0; mt < 2; mt++) {
                    unsigned p1[4], p2[4], a[4];
                    unsigned ab = pb + (mt * 16 * PAD_P + kt * 16) * 2;
                    ldmx4(p1, ab);
                    ldmx4(p2, ab + 128);
                    a[0] = hrelu2u(hadd2u(hadd2u(p1[0], p2[0]), bias1u[kt][0]));
                    a[1] = hrelu2u(hadd2u(hadd2u(p1[1], p2[1]), bias1u[kt][0]));
                    a[2] = hrelu2u(hadd2u(hadd2u(p1[2], p2[2]), bias1u[kt][1]));
                    a[3] = hrelu2u(hadd2u(hadd2u(p1[3], p2[3]), bias1u[kt][1]));
                    mma_f16(macc[sub][mt][0], a, wb2[kt][0]);
                    mma_f16(macc[sub][mt][1], a, wb2[kt][1]);
                }
            }

            float* sEs = sE + buf * 128 + sub * 64;
#pragma unroll
            for (int mt = 0; mt < 2; mt++) {
                int r = wm * 32 + mt * 16 + laned4;
                float plo = 0.0f, phi = 0.0f;
#pragma unroll
                for (int nt = 0; nt < 2; nt++) {
                    macc[sub][mt][nt][0] = fmaxf(macc[sub][mt][nt][0], 0.0f);
                    macc[sub][mt][nt][1] = fmaxf(macc[sub][mt][nt][1], 0.0f);
                    macc[sub][mt][nt][2] = fmaxf(macc[sub][mt][nt][2], 0.0f);
                    macc[sub][mt][nt][3] = fmaxf(macc[sub][mt][nt][3], 0.0f);
                    plo += macc[sub][mt][nt][0] * wf[nt][0] + macc[sub][mt][nt][1] * wf[nt][1];
                    phi += macc[sub][mt][nt][2] * wf[nt][0] + macc[sub][mt][nt][3] * wf[nt][1];
                }
                plo += __shfl_xor_sync(0xffffffffu, plo, 1);
                plo += __shfl_xor_sync(0xffffffffu, plo, 2);
                phi += __shfl_xor_sync(0xffffffffu, phi, 1);
                phi += __shfl_xor_sync(0xffffffffu, phi, 2);
                if (lane4 == 0) {
                    atomicAdd(&sEs[r], plo);
                    atomicAdd(&sEs[r + 8], phi);
                }
            }
        }
        __syncthreads();   // both subs' sE complete

        // ---- gate + fp16x2 atomic scatter (half bytes vs v2.f32) ----
#pragma unroll
        for (int sub = 0; sub < 2; sub++) {
            float* sEs = sE + buf * 128 + sub * 64;
            float* sDs = sDis + buf * 128 + sub * 64;
            int*   sDt = sDst + buf * 128 + sub * 64;
#pragma unroll
            for (int mt = 0; mt < 2; mt++) {
                int r = wm * 32 + mt * 16 + laned4;
                float w1 = fast_sigmoid(sEs[r] * sDs[r]);
                float w2 = fast_sigmoid(sEs[r + 8] * sDs[r + 8]);
                half* p1 = g_mi16 + (size_t)sDt[r] * H;
                half* p2 = g_mi16 + (size_t)sDt[r + 8] * H;
#pragma unroll
                for (int nt = 0; nt < 2; nt++) {
                    int c = wn * 16 + nt * 8 + 2 * lane4;
                    red_f16x2(p1 + c, macc[sub][mt][nt][0] * w1, macc[sub][mt][nt][1] * w1);
                    red_f16x2(p2 + c, macc[sub][mt][nt][2] * w2, macc[sub][mt][nt][3] * w2);
                }
            }
        }
    }
}

// ---------------------------------------------------------------------------
// Node kernel: layer1 = relu(mi@Wn1_top + g_q)  (g_q has h-part + bn1 folded)
// ---------------------------------------------------------------------------
#define WARPS 8
#define EPT 8
#define NK_SMEM_FLOATS (4352 + 4352 + 192 + 8192 + 4096)
#define NK_SMEM_BYTES  (NK_SMEM_FLOATS * 4)

__global__ void __launch_bounds__(256, 2) node_kernel(
    const float* __restrict__ h,
    const float* __restrict__ Wn1,
    const float* __restrict__ Wn2, const float* __restrict__ bn2,
    const float* __restrict__ lng, const float* __restrict__ lnb,
    float* __restrict__ out)
{
    extern __shared__ float smem[];
    float* sW1 = smem;              // Wn1_top transposed [64][68]
    float* sW2 = sW1 + 64 * 68;     // Wn2 transposed [64][68]
    float* sB2 = sW2 + 64 * 68;
    float* sG  = sB2 + 64;
    float* sB  = sG + 64;
    float* sIn = sB + 64;           // 8*1024
    float* sT  = sIn + 8 * 1024;    // 8*512

    const int tid = threadIdx.x;
    for (int i = tid; i < 64 * 64; i += 256) {
        int k = i >> 6, c = i & 63;
        sW1[c * 68 + k] = Wn1[i];          // top half rows k<64
        sW2[c * 68 + k] = Wn2[i];
    }
    if (tid < 64) { sB2[tid] = bn2[tid]; sG[tid] = lng[tid]; sB[tid] = lnb[tid]; }
    __syncthreads();

    const int warp = tid >> 5, lane = tid & 31;
    const int c0 = lane, c1 = lane + 32;
    const float b2_0 = sB2[c0], b2_1 = sB2[c1];
    const float g0 = sG[c0], g1 = sG[c1];
    const float bb0 = sB[c0], bb1 = sB[c1];
    float* myIn = sIn + warp * 1024;
    float* myT  = sT + warp * 512;

    const int gw = blockIdx.x * WARPS + warp;
    const int nwarps = gridDim.x * WARPS;

    for (int base = gw * EPT; base < NN; base += nwarps * EPT) {
#pragma unroll
        for (int e = 0; e < EPT; e++) {
            const half*  mip = g_mi16 + (size_t)(base + e) * H;
            const float* hp  = h + (size_t)(base + e) * H;
            float2 mv = __half22float2(*reinterpret_cast<const half2*>(mip + 2 * lane));
            *reinterpret_cast<float2*>(myIn + e * 128 + 2 * lane) = mv;
            *reinterpret_cast<float2*>(myIn + e * 128 + 64 + 2 * lane) =
                *reinterpret_cast<const float2*>(hp + 2 * lane);
        }
        __syncwarp();

        // layer1: a = mi@Wn1_top + g_q   (g_q includes h-part + bn1)
        float a0[EPT], a1[EPT];
#pragma unroll
        for (int e = 0; e < EPT; e++) {
            const float* qp = g_q + (size_t)(base + e) * 64;
            a0[e] = qp[c0]; a1[e] = qp[c1];
        }
#pragma unroll 2
        for (int k = 0; k < 64; k += 4) {
            float4 w0 = *reinterpret_cast<const float4*>(sW1 + c0 * 68 + k);
            float4 w1 = *reinterpret_cast<const float4*>(sW1 + c1 * 68 + k);
#pragma unroll
            for (int e = 0; e < EPT; e++) {
                float4 v = *reinterpret_cast<const float4*>(myIn + e * 128 + k);
                a0[e] = fmaf(v.x, w0.x, a0[e]); a0[e] = fmaf(v.y, w0.y, a0[e]);
                a0[e] = fmaf(v.z, w0.z, a0[e]); a0[e] = fmaf(v.w, w0.w, a0[e]);
                a1[e] = fmaf(v.x, w1.x, a1[e]); a1[e] = fmaf(v.y, w1.y, a1[e]);
                a1[e] = fmaf(v.z, w1.z, a1[e]); a1[e] = fmaf(v.w, w1.w, a1[e]);
            }
        }
#pragma unroll
        for (int e = 0; e < EPT; e++) {
            myT[e * 64 + c0] = fmaxf(a0[e], 0.0f);
            myT[e * 64 + c1] = fmaxf(a1[e], 0.0f);
        }
        __syncwarp();

        float u0[EPT], u1[EPT];
#pragma unroll
        for (int e = 0; e < EPT; e++) { u0[e] = b2_0; u1[e] = b2_1; }
#pragma unroll 2
        for (int k = 0; k < 64; k += 4) {
            float4 w0 = *reinterpret_cast<const float4*>(sW2 + c0 * 68 + k);
            float4 w1 = *reinterpret_cast<const float4*>(sW2 + c1 * 68 + k);
#pragma unroll
            for (int e = 0; e < EPT; e++) {
                float4 v = *reinterpret_cast<const float4*>(myT + e * 64 + k);
                u0[e] = fmaf(v.x, w0.x, u0[e]); u0[e] = fmaf(v.y, w0.y, u0[e]);
                u0[e] = fmaf(v.z, w0.z, u0[e]); u0[e] = fmaf(v.w, w0.w, u0[e]);
                u1[e] = fmaf(v.x, w1.x, u1[e]); u1[e] = fmaf(v.y, w1.y, u1[e]);
                u1[e] = fmaf(v.w, w1.w, u1[e]); u1[e] = fmaf(v.z, w1.z, u1[e]);
            }
        }

#pragma unroll
        for (int e = 0; e < EPT; e++) {
            float z0 = u0[e] + myIn[e * 128 + 64 + c0];
            float z1 = u1[e] + myIn[e * 128 + 64 + c1];
            float s = z0 + z1;
            float q = z0 * z0 + z1 * z1;
#pragma unroll
            for (int o = 16; o > 0; o >>= 1) {
                s += __shfl_xor_sync(0xffffffffu, s, o);
                q += __shfl_xor_sync(0xffffffffu, q, o);
            }
            float mean = s * (1.0f / 64.0f);
            float var = q * (1.0f / 64.0f) - mean * mean;
            float inv = rsqrtf(var + 1e-5f);
            size_t ro = (size_t)(base + e) * H;
            out[ro + c0] = (z0 - mean) * inv * g0 + bb0;
            out[ro + c1] = (z1 - mean) * inv * g1 + bb1;
        }
        __syncwarp();
    }
}

__global__ void copy_x_kernel(const float4* __restrict__ x, float4* __restrict__ out)
{
    int i = blockIdx.x * blockDim.x + threadIdx.x;
    if (i < (NN * 3) / 4) out[i] = x[i];
}

extern "C" void kernel_launch(void* const* d_in, const int* in_sizes, int n_in,
                              void* d_out, int out_size)
{
    const float* h    = (const float*)d_in[0];
    const float* x    = (const float*)d_in[1];
    const int*   ei   = (const int*)d_in[2];
    const float* We1  = (const float*)d_in[3];
    const float* be1  = (const float*)d_in[4];
    const float* We2  = (const float*)d_in[5];
    const float* be2  = (const float*)d_in[6];
    const float* Winf = (const float*)d_in[7];
    const float* binf = (const float*)d_in[8];
    const float* Wn1  = (const float*)d_in[9];
    const float* bn1  = (const float*)d_in[10];
    const float* Wn2  = (const float*)d_in[11];
    const float* bn2  = (const float*)d_in[12];
    const float* lng  = (const float*)d_in[13];
    const float* lnb  = (const float*)d_in[14];
    float* out = (float*)d_out;

    void* mi_ptr = nullptr;
    cudaGetSymbolAddress(&mi_ptr, g_mi16);
    cudaMemsetAsync(mi_ptr, 0, sizeof(half) * (size_t)NN * H, 0);
    precompute_kernel<<<(NN + 63) / 64, 256>>>(h, We1, Wn1, bn1);

    cudaFuncSetAttribute(edge_mma_kernel, cudaFuncAttributeMaxDynamicSharedMemorySize, EK_SMEM_BYTES);
    cudaFuncSetAttribute(node_kernel, cudaFuncAttributeMaxDynamicSharedMemorySize, NK_SMEM_BYTES);

    edge_mma_kernel<<<296, 256, EK_SMEM_BYTES>>>(x, ei, be1, We2, be2, Winf, binf);
    node_kernel<<<296, 256, NK_SMEM_BYTES>>>(h, Wn1, Wn2, bn2, lng, lnb, out);

    if (out_size >= NN * H + NN * 3) {
        copy_x_kernel<<<(NN * 3 / 4 + 255) / 256, 256>>>((const float4*)x,
                                                         (float4*)(out + (size_t)NN * H));
    }
}

// round 15
// speedup vs baseline: 1.2739x; 1.1180x over previous
#include <cuda_runtime.h>
#include <cuda_fp16.h>
#include <cstdint>

#define H 64
#define NN 100000
#define NE 1600000

// device-global scratch (no allocation allowed)
__device__ half  g_mi16[(size_t)NN * H];  // fp16 segment-sum accumulator
__device__ half  g_p[(size_t)NN * 128];   // [P1 | P2] per node (edge MLP layer-1)
__device__ float g_q[(size_t)NN * 64];    // h@Wn1_bot + bn1 (node MLP layer-1 part)

__device__ __forceinline__ float fast_sigmoid(float z) {
    return 1.0f / (1.0f + __expf(-z));
}
__device__ __forceinline__ void mma_f16(float c[4], const unsigned a[4], const unsigned b[2]) {
    asm volatile("mma.sync.aligned.m16n8k16.row.col.f32.f16.f16.f32 "
        "{%0,%1,%2,%3}, {%4,%5,%6,%7}, {%8,%9}, {%0,%1,%2,%3};"
        : "+f"(c[0]), "+f"(c[1]), "+f"(c[2]), "+f"(c[3])
        : "r"(a[0]), "r"(a[1]), "r"(a[2]), "r"(a[3]), "r"(b[0]), "r"(b[1]));
}
__device__ __forceinline__ void ldmx4(unsigned a[4], unsigned saddr) {
    asm volatile("ldmatrix.sync.aligned.m8n8.x4.shared.b16 {%0,%1,%2,%3}, [%4];"
        : "=r"(a[0]), "=r"(a[1]), "=r"(a[2]), "=r"(a[3]) : "r"(saddr));
}
__device__ __forceinline__ void ldmx2(unsigned b[2], unsigned saddr) {
    asm volatile("ldmatrix.sync.aligned.m8n8.x2.shared.b16 {%0,%1}, [%2];"
        : "=r"(b[0]), "=r"(b[1]) : "r"(saddr));
}
__device__ __forceinline__ unsigned h2u(half2 v) { return *reinterpret_cast<unsigned*>(&v); }
__device__ __forceinline__ void cpasync16(unsigned dst, const void* src) {
    asm volatile("cp.async.cg.shared.global [%0], [%1], 16;" :: "r"(dst), "l"(src));
}
__device__ __forceinline__ unsigned hadd2u(unsigned a, unsigned b) {
    unsigned r; asm("add.f16x2 %0, %1, %2;" : "=r"(r) : "r"(a), "r"(b)); return r;
}
__device__ __forceinline__ unsigned hrelu2u(unsigned a) {
    unsigned r; asm("max.f16x2 %0, %1, %2;" : "=r"(r) : "r"(a), "r"(0u)); return r;
}
__device__ __forceinline__ void red_f16x2(half* p, float lo, float hi) {
    unsigned v = h2u(__floats2half2_rn(lo, hi));
    asm volatile("red.global.add.noftz.f16x2 [%0], %1;" :: "l"(p), "r"(v) : "memory");
}

// ---------------------------------------------------------------------------
// Precompute per node (64 nodes/block):
//   g_p[n][0:64]   = h[n] @ We1_top       (fp16)
//   g_p[n][64:128] = h[n] @ We1_bot       (fp16)
//   g_q[n][0:64]   = h[n] @ Wn1_bot + bn1 (fp32)
// ---------------------------------------------------------------------------
__global__ void __launch_bounds__(256) precompute_kernel(
    const float* __restrict__ h, const float* __restrict__ We1,
    const float* __restrict__ Wn1, const float* __restrict__ bn1)
{
    __shared__ half sAh[64 * 72];
    const int tid = threadIdx.x;
    const int warp = tid >> 5, lane = tid & 31;
    const int lane4 = lane & 3, laned4 = lane >> 2;
    const int wm = warp & 1, wn = warp >> 1;   // 32 rows x 48 out-cols per warp

    unsigned wb[4][6][2];
#pragma unroll
    for (int kt = 0; kt < 4; kt++)
#pragma unroll
        for (int nt = 0; nt < 6; nt++) {
            int j = wn * 48 + nt * 8 + laned4;      // 0..191 output col
            int k = kt * 16 + 2 * lane4;
            float w00, w01, w10, w11;
            if (j < 128) {
                int kr = k + ((j >= 64) ? 64 : 0);
                int jc = j & 63;
                w00 = We1[kr * 64 + jc];       w01 = We1[(kr + 1) * 64 + jc];
                w10 = We1[(kr + 8) * 64 + jc]; w11 = We1[(kr + 9) * 64 + jc];
            } else {
                int jc = j - 128;
                w00 = Wn1[(k + 64) * 64 + jc];     w01 = Wn1[(k + 65) * 64 + jc];
                w10 = Wn1[(k + 72) * 64 + jc];     w11 = Wn1[(k + 73) * 64 + jc];
            }
            wb[kt][nt][0] = h2u(__floats2half2_rn(w00, w01));
            wb[kt][nt][1] = h2u(__floats2half2_rn(w10, w11));
        }

    const int node0 = blockIdx.x * 64;
    {
        int nd = tid >> 2, q = tid & 3;
        if (node0 + nd < NN) {
            const float* src = h + (size_t)(node0 + nd) * H + q * 16;
            half* dst = sAh + nd * 72 + q * 16;
#pragma unroll
            for (int j = 0; j < 4; j++) {
                float4 v = *reinterpret_cast<const float4*>(src + j * 4);
                *reinterpret_cast<half2*>(dst + j * 4)     = __floats2half2_rn(v.x, v.y);
                *reinterpret_cast<half2*>(dst + j * 4 + 2) = __floats2half2_rn(v.z, v.w);
            }
        }
    }
    __syncthreads();

    const int al = lane & 15, ah = lane >> 4;
    unsigned abase = (unsigned)__cvta_generic_to_shared(sAh) + ((wm * 32 + al) * 72 + ah * 8) * 2;
    float acc[2][6][4] = {};
#pragma unroll
    for (int kt = 0; kt < 4; kt++)
#pragma unroll
        for (int mt = 0; mt < 2; mt++) {
            unsigned a[4];
            ldmx4(a, abase + (mt * 16 * 72 + kt * 16) * 2);
#pragma unroll
            for (int nt = 0; nt < 6; nt++)
                mma_f16(acc[mt][nt], a, wb[kt][nt]);
        }
#pragma unroll
    for (int mt = 0; mt < 2; mt++)
#pragma unroll
        for (int nt = 0; nt < 6; nt++) {
            int r = wm * 32 + mt * 16 + laned4;
            int c = wn * 48 + nt * 8 + 2 * lane4;
            if (c < 128) {
                if (node0 + r < NN)
                    *reinterpret_cast<half2*>(g_p + (size_t)(node0 + r) * 128 + c) =
                        __floats2half2_rn(acc[mt][nt][0], acc[mt][nt][1]);
                if (node0 + r + 8 < NN)
                    *reinterpret_cast<half2*>(g_p + (size_t)(node0 + r + 8) * 128 + c) =
                        __floats2half2_rn(acc[mt][nt][2], acc[mt][nt][3]);
            } else {
                int cq = c - 128;
                float b0 = bn1[cq], b1 = bn1[cq + 1];
                if (node0 + r < NN)
                    *reinterpret_cast<float2*>(g_q + (size_t)(node0 + r) * 64 + cq) =
                        make_float2(acc[mt][nt][0] + b0, acc[mt][nt][1] + b1);
                if (node0 + r + 8 < NN)
                    *reinterpret_cast<float2*>(g_q + (size_t)(node0 + r + 8) * 64 + cq) =
                        make_float2(acc[mt][nt][2] + b0, acc[mt][nt][3] + b1);
            }
        }
}

// ---------------------------------------------------------------------------
// Edge kernel: row-major warp layout. Each warp owns 16 edges x 64 cols:
// gate is quad-local (no smem atomics, no mid barrier); 1 barrier/super-tile.
// ---------------------------------------------------------------------------
#define TILE_E 128        // 2 subtiles of 64
#define PAD_P 136         // halves/row (272B): conflict-free ldmatrix
#define PAD_W 72          // W2^T halves/row (144B)
#define SP_BYTES (64 * PAD_P * 2)
// sP[2 bufs][2 subs] | sW2t | sDis[2][128] | sDst[2][128]
#define EK_SMEM_BYTES (4*SP_BYTES + 64*PAD_W*2 + 2*128*4*2)

__global__ void __launch_bounds__(256, 2) edge_mma_kernel(
    const float* __restrict__ x,
    const int* __restrict__ edge_index,
    const float* __restrict__ be1,
    const float* __restrict__ We2, const float* __restrict__ be2,
    const float* __restrict__ Winf, const float* __restrict__ binf)
{
    extern __shared__ char smraw[];
    half*  sP   = (half*)smraw;                      // [4][64][136]  (buf*2+sub)
    half*  sW2t = sP + 4 * 64 * PAD_P;               // [64][72] W2^T [n][k]
    float* sDis = (float*)(sW2t + 64 * PAD_W);       // [2][128]
    int*   sDst = (int*)(sDis + 256);                // [2][128]

    const int tid  = threadIdx.x;
    const int warp = tid >> 5, lane = tid & 31;
    const int lane4 = lane & 3, laned4 = lane >> 2;
    const int wsub = warp >> 2;        // which subtile (0/1)
    const int wrow = (warp & 3) * 16;  // row base within subtile

    // stage W2^T into smem (fp16), once per block
    for (int i = tid; i < 64 * 64; i += 256) {
        int k = i >> 6, n = i & 63;
        sW2t[n * PAD_W + k] = __float2half_rn(We2[i]);
    }

    // be1 in A-fragment layout
    unsigned bias1u[4][2];
#pragma unroll
    for (int kt = 0; kt < 4; kt++) {
        int k = kt * 16 + 2 * lane4;
        bias1u[kt][0] = h2u(__floats2half2_rn(be1[k], be1[k + 1]));
        bias1u[kt][1] = h2u(__floats2half2_rn(be1[k + 8], be1[k + 9]));
    }
    // full-width bias2 / Winf per lane (2 cols per nt)
    float bias2v[8][2], wfv[8][2];
#pragma unroll
    for (int nt = 0; nt < 8; nt++) {
        int c = nt * 8 + 2 * lane4;
        bias2v[nt][0] = be2[c]; bias2v[nt][1] = be2[c + 1];
        wfv[nt][0]    = Winf[c]; wfv[nt][1]   = Winf[c + 1];
    }
    const float binf0 = binf[0];

    unsigned sP_s = (unsigned)__cvta_generic_to_shared(sP);
    unsigned sW_s = (unsigned)__cvta_generic_to_shared(sW2t);
    const int al = lane & 15, ah = lane >> 4;
    const unsigned aoff_l = (unsigned)(((wrow + al) * PAD_P + ah * 8) * 2);
    const int bl = lane & 15;
    const unsigned boff_l = (unsigned)((((bl & 7)) * PAD_W + (bl >> 3) * 8) * 2);

    const int se = tid >> 2;
    const int sp = tid & 3;

    auto prefetch = [&](int t, int b) {
        const int base = t * TILE_E;
#pragma unroll
        for (int sub = 0; sub < 2; sub++) {
            int g = base + sub * 64 + se;
            int s = edge_index[g];
            int d = edge_index[NE + g];
            int idx = (sp < 2) ? d : s;
            const half* srcp = g_p + (size_t)idx * 128 + sp * 32;
            unsigned dp = sP_s + (unsigned)((b * 2 + sub) * SP_BYTES)
                        + (unsigned)((se * PAD_P + sp * 32) * 2);
#pragma unroll
            for (int j = 0; j < 4; j++) cpasync16(dp + j * 16, srcp + j * 8);
        }
        asm volatile("cp.async.commit_group;");
        if (tid < 128) {
            int s2 = edge_index[base + tid];
            int d2 = edge_index[NE + base + tid];
            sDst[b * 128 + tid] = d2;
            float dx = x[d2 * 3 + 0] - x[s2 * 3 + 0];
            float dy = x[d2 * 3 + 1] - x[s2 * 3 + 1];
            float dz = x[d2 * 3 + 2] - x[s2 * 3 + 2];
            float dd = dx * dx + dy * dy + dz * dz;
            sDis[b * 128 + tid] = fast_sigmoid(30.0f / (sqrtf(dd) + 1e-8f));
        }
    };

    const int ntiles = NE / TILE_E;
    int t = blockIdx.x;
    if (t < ntiles) prefetch(t, 0);
    int buf = 0;

    for (; t < ntiles; t += gridDim.x, buf ^= 1) {
        asm volatile("cp.async.wait_group 0;");
        __syncthreads();   // sP[buf]+scalars visible; prev buffers fully consumed
                           // (also covers initial W2^T staging)

        // prefetch next super-tile into other buffer
        {
            int tn = t + gridDim.x;
            if (tn < ntiles) prefetch(tn, buf ^ 1);
        }

        // ---- this warp's 16 rows: GEMM2 over all 64 cols, fused layer-1 ----
        const unsigned pb = sP_s + (unsigned)((buf * 2 + wsub) * SP_BYTES) + aoff_l;
        float macc[8][4];
#pragma unroll
        for (int nt = 0; nt < 8; nt++) {
            macc[nt][0] = bias2v[nt][0]; macc[nt][1] = bias2v[nt][1];
            macc[nt][2] = bias2v[nt][0]; macc[nt][3] = bias2v[nt][1];
        }
#pragma unroll
        for (int kt = 0; kt < 4; kt++) {
            unsigned p1[4], p2[4], a[4];
            unsigned ab = pb + (kt * 16) * 2;
            ldmx4(p1, ab);
            ldmx4(p2, ab + 128);   // P2 lives 64 halves later in the row
            a[0] = hrelu2u(hadd2u(hadd2u(p1[0], p2[0]), bias1u[kt][0]));
            a[1] = hrelu2u(hadd2u(hadd2u(p1[1], p2[1]), bias1u[kt][0]));
            a[2] = hrelu2u(hadd2u(hadd2u(p1[2], p2[2]), bias1u[kt][1]));
            a[3] = hrelu2u(hadd2u(hadd2u(p1[3], p2[3]), bias1u[kt][1]));
#pragma unroll
            for (int nt = 0; nt < 8; nt++) {
                unsigned b[2];
                ldmx2(b, sW_s + boff_l + (unsigned)((nt * 8 * PAD_W + kt * 16) * 2));
                mma_f16(macc[nt], a, b);
            }
        }

        // ---- relu + quad-local gate ----
        float plo = 0.0f, phi = 0.0f;
#pragma unroll
        for (int nt = 0; nt < 8; nt++) {
            macc[nt][0] = fmaxf(macc[nt][0], 0.0f);
            macc[nt][1] = fmaxf(macc[nt][1], 0.0f);
            macc[nt][2] = fmaxf(macc[nt][2], 0.0f);
            macc[nt][3] = fmaxf(macc[nt][3], 0.0f);
            plo += macc[nt][0] * wfv[nt][0] + macc[nt][1] * wfv[nt][1];
            phi += macc[nt][2] * wfv[nt][0] + macc[nt][3] * wfv[nt][1];
        }
        plo += __shfl_xor_sync(0xffffffffu, plo, 1);
        plo += __shfl_xor_sync(0xffffffffu, plo, 2);
        phi += __shfl_xor_sync(0xffffffffu, phi, 1);
        phi += __shfl_xor_sync(0xffffffffu, phi, 2);

        const int rl = wsub * 64 + wrow + laned4;   // row in super-tile
        float w1 = fast_sigmoid((plo + binf0) * sDis[buf * 128 + rl]);
        float w2 = fast_sigmoid((phi + binf0) * sDis[buf * 128 + rl + 8]);
        half* p1 = g_mi16 + (size_t)sDst[buf * 128 + rl] * H;
        half* p2 = g_mi16 + (size_t)sDst[buf * 128 + rl + 8] * H;

        // ---- fp16x2 atomic scatter (warp-independent, fire-and-forget) ----
#pragma unroll
        for (int nt = 0; nt < 8; nt++) {
            int c = nt * 8 + 2 * lane4;
            red_f16x2(p1 + c, macc[nt][0] * w1, macc[nt][1] * w1);
            red_f16x2(p2 + c, macc[nt][2] * w2, macc[nt][3] * w2);
        }
    }
}

// ---------------------------------------------------------------------------
// Node kernel: layer1 = relu(mi@Wn1_top + g_q)  (g_q has h-part + bn1 folded)
// ---------------------------------------------------------------------------
#define WARPS 8
#define EPT 8
#define NK_SMEM_FLOATS (4352 + 4352 + 192 + 8192 + 4096)
#define NK_SMEM_BYTES  (NK_SMEM_FLOATS * 4)

__global__ void __launch_bounds__(256, 2) node_kernel(
    const float* __restrict__ h,
    const float* __restrict__ Wn1,
    const float* __restrict__ Wn2, const float* __restrict__ bn2,
    const float* __restrict__ lng, const float* __restrict__ lnb,
    float* __restrict__ out)
{
    extern __shared__ float smem[];
    float* sW1 = smem;              // Wn1_top transposed [64][68]
    float* sW2 = sW1 + 64 * 68;     // Wn2 transposed [64][68]
    float* sB2 = sW2 + 64 * 68;
    float* sG  = sB2 + 64;
    float* sB  = sG + 64;
    float* sIn = sB + 64;           // 8*1024
    float* sT  = sIn + 8 * 1024;    // 8*512

    const int tid = threadIdx.x;
    for (int i = tid; i < 64 * 64; i += 256) {
        int k = i >> 6, c = i & 63;
        sW1[c * 68 + k] = Wn1[i];          // top half rows k<64
        sW2[c * 68 + k] = Wn2[i];
    }
    if (tid < 64) { sB2[tid] = bn2[tid]; sG[tid] = lng[tid]; sB[tid] = lnb[tid]; }
    __syncthreads();

    const int warp = tid >> 5, lane = tid & 31;
    const int c0 = lane, c1 = lane + 32;
    const float b2_0 = sB2[c0], b2_1 = sB2[c1];
    const float g0 = sG[c0], g1 = sG[c1];
    const float bb0 = sB[c0], bb1 = sB[c1];
    float* myIn = sIn + warp * 1024;
    float* myT  = sT + warp * 512;

    const int gw = blockIdx.x * WARPS + warp;
    const int nwarps = gridDim.x * WARPS;

    for (int base = gw * EPT; base < NN; base += nwarps * EPT) {
#pragma unroll
        for (int e = 0; e < EPT; e++) {
            const half*  mip = g_mi16 + (size_t)(base + e) * H;
            const float* hp  = h + (size_t)(base + e) * H;
            float2 mv = __half22float2(*reinterpret_cast<const half2*>(mip + 2 * lane));
            *reinterpret_cast<float2*>(myIn + e * 128 + 2 * lane) = mv;
            *reinterpret_cast<float2*>(myIn + e * 128 + 64 + 2 * lane) =
                *reinterpret_cast<const float2*>(hp + 2 * lane);
        }
        __syncwarp();

        // layer1: a = mi@Wn1_top + g_q   (g_q includes h-part + bn1)
        float a0[EPT], a1[EPT];
#pragma unroll
        for (int e = 0; e < EPT; e++) {
            const float* qp = g_q + (size_t)(base + e) * 64;
            a0[e] = qp[c0]; a1[e] = qp[c1];
        }
#pragma unroll 2
        for (int k = 0; k < 64; k += 4) {
            float4 w0 = *reinterpret_cast<const float4*>(sW1 + c0 * 68 + k);
            float4 w1 = *reinterpret_cast<const float4*>(sW1 + c1 * 68 + k);
#pragma unroll
            for (int e = 0; e < EPT; e++) {
                float4 v = *reinterpret_cast<const float4*>(myIn + e * 128 + k);
                a0[e] = fmaf(v.x, w0.x, a0[e]); a0[e] = fmaf(v.y, w0.y, a0[e]);
                a0[e] = fmaf(v.z, w0.z, a0[e]); a0[e] = fmaf(v.w, w0.w, a0[e]);
                a1[e] = fmaf(v.x, w1.x, a1[e]); a1[e] = fmaf(v.y, w1.y, a1[e]);
                a1[e] = fmaf(v.z, w1.z, a1[e]); a1[e] = fmaf(v.w, w1.w, a1[e]);
            }
        }
#pragma unroll
        for (int e = 0; e < EPT; e++) {
            myT[e * 64 + c0] = fmaxf(a0[e], 0.0f);
            myT[e * 64 + c1] = fmaxf(a1[e], 0.0f);
        }
        __syncwarp();

        float u0[EPT], u1[EPT];
#pragma unroll
        for (int e = 0; e < EPT; e++) { u0[e] = b2_0; u1[e] = b2_1; }
#pragma unroll 2
        for (int k = 0; k < 64; k += 4) {
            float4 w0 = *reinterpret_cast<const float4*>(sW2 + c0 * 68 + k);
            float4 w1 = *reinterpret_cast<const float4*>(sW2 + c1 * 68 + k);
#pragma unroll
            for (int e = 0; e < EPT; e++) {
                float4 v = *reinterpret_cast<const float4*>(myT + e * 64 + k);
                u0[e] = fmaf(v.x, w0.x, u0[e]); u0[e] = fmaf(v.y, w0.y, u0[e]);
                u0[e] = fmaf(v.z, w0.z, u0[e]); u0[e] = fmaf(v.w, w0.w, u0[e]);
                u1[e] = fmaf(v.x, w1.x, u1[e]); u1[e] = fmaf(v.y, w1.y, u1[e]);
                u1[e] = fmaf(v.z, w1.z, u1[e]); u1[e] = fmaf(v.w, w1.w, u1[e]);
            }
        }

#pragma unroll
        for (int e = 0; e < EPT; e++) {
            float z0 = u0[e] + myIn[e * 128 + 64 + c0];
            float z1 = u1[e] + myIn[e * 128 + 64 + c1];
            float s = z0 + z1;
            float q = z0 * z0 + z1 * z1;
#pragma unroll
            for (int o = 16; o > 0; o >>= 1) {
                s += __shfl_xor_sync(0xffffffffu, s, o);
                q += __shfl_xor_sync(0xffffffffu, q, o);
            }
            float mean = s * (1.0f / 64.0f);
            float var = q * (1.0f / 64.0f) - mean * mean;
            float inv = rsqrtf(var + 1e-5f);
            size_t ro = (size_t)(base + e) * H;
            out[ro + c0] = (z0 - mean) * inv * g0 + bb0;
            out[ro + c1] = (z1 - mean) * inv * g1 + bb1;
        }
        __syncwarp();
    }
}

__global__ void copy_x_kernel(const float4* __restrict__ x, float4* __restrict__ out)
{
    int i = blockIdx.x * blockDim.x + threadIdx.x;
    if (i < (NN * 3) / 4) out[i] = x[i];
}

extern "C" void kernel_launch(void* const* d_in, const int* in_sizes, int n_in,
                              void* d_out, int out_size)
{
    const float* h    = (const float*)d_in[0];
    const float* x    = (const float*)d_in[1];
    const int*   ei   = (const int*)d_in[2];
    const float* We1  = (const float*)d_in[3];
    const float* be1  = (const float*)d_in[4];
    const float* We2  = (const float*)d_in[5];
    const float* be2  = (const float*)d_in[6];
    const float* Winf = (const float*)d_in[7];
    const float* binf = (const float*)d_in[8];
    const float* Wn1  = (const float*)d_in[9];
    const float* bn1  = (const float*)d_in[10];
    const float* Wn2  = (const float*)d_in[11];
    const float* bn2  = (const float*)d_in[12];
    const float* lng  = (const float*)d_in[13];
    const float* lnb  = (const float*)d_in[14];
    float* out = (float*)d_out;

    void* mi_ptr = nullptr;
    cudaGetSymbolAddress(&mi_ptr, g_mi16);
    cudaMemsetAsync(mi_ptr, 0, sizeof(half) * (size_t)NN * H, 0);
    precompute_kernel<<<(NN + 63) / 64, 256>>>(h, We1, Wn1, bn1);

    cudaFuncSetAttribute(edge_mma_kernel, cudaFuncAttributeMaxDynamicSharedMemorySize, EK_SMEM_BYTES);
    cudaFuncSetAttribute(node_kernel, cudaFuncAttributeMaxDynamicSharedMemorySize, NK_SMEM_BYTES);

    edge_mma_kernel<<<296, 256, EK_SMEM_BYTES>>>(x, ei, be1, We2, be2, Winf, binf);
    node_kernel<<<296, 256, NK_SMEM_BYTES>>>(h, Wn1, Wn2, bn2, lng, lnb, out);

    if (out_size >= NN * H + NN * 3) {
        copy_x_kernel<<<(NN * 3 / 4 + 255) / 256, 256>>>((const float4*)x,
                                                         (float4*)(out + (size_t)NN * H));
    }
}